// round 14
// baseline (speedup 1.0000x reference)
#include <cuda_runtime.h>
#include <cuda_bf16.h>
#include <cuda_fp16.h>
#include <cstdint>

// Problem constants
#define Bb 4
#define Cc 64
#define NA 25
#define HW 4096
#define Dd 64
#define Oo 192

// ---------------------------------------------------------------------------
// Scratch (device globals -- no runtime allocation allowed)
// ---------------------------------------------------------------------------
__device__ __nv_bfloat16 g_q[(size_t)Bb * NA * HW * Dd];   // [b][n][px][d] 52MB
__device__ __nv_bfloat16 g_k[(size_t)Bb * NA * HW * Dd];   // 52MB
__device__ __half g_v[(size_t)Bb * Dd * NA * HW];          // [b][d][n][px] 52MB fp16
__device__ float g_gp[(size_t)Bb * 128 * 1088];            // per-(b,chunk): S 32x32 + qn2 + kn2
__device__ float g_att[Bb * NA * NA];

// ---------------------------------------------------------------------------
// Helpers: ldmatrix + mma.sync (plain sm_80+ PTX -- compiles on compute_103)
// ---------------------------------------------------------------------------
__device__ __forceinline__ uint32_t smem_u32(const void* p) {
    uint32_t a;
    asm("{ .reg .u64 t; cvta.to.shared.u64 t, %1; cvt.u32.u64 %0, t; }" : "=r"(a) : "l"(p));
    return a;
}
#define LDSM_X4(r, addr)                                                       \
    asm volatile("ldmatrix.sync.aligned.m8n8.x4.shared.b16 {%0,%1,%2,%3}, [%4];" \
                 : "=r"((r)[0]), "=r"((r)[1]), "=r"((r)[2]), "=r"((r)[3])      \
                 : "r"(addr))
#define LDSM_X4_T(r, addr)                                                     \
    asm volatile("ldmatrix.sync.aligned.m8n8.x4.trans.shared.b16 {%0,%1,%2,%3}, [%4];" \
                 : "=r"((r)[0]), "=r"((r)[1]), "=r"((r)[2]), "=r"((r)[3])      \
                 : "r"(addr))
__device__ __forceinline__ void mma16816(float* c, const uint32_t* a,
                                         uint32_t b0, uint32_t b1) {
    asm volatile(
        "mma.sync.aligned.m16n8k16.row.col.f32.bf16.bf16.f32 "
        "{%0,%1,%2,%3}, {%4,%5,%6,%7}, {%8,%9}, {%0,%1,%2,%3};"
        : "+f"(c[0]), "+f"(c[1]), "+f"(c[2]), "+f"(c[3])
        : "r"(a[0]), "r"(a[1]), "r"(a[2]), "r"(a[3]), "r"(b0), "r"(b1));
}
__device__ __forceinline__ uint32_t packbf2(float x, float y) {
    __nv_bfloat162 t;
    t.x = __float2bfloat16(x);
    t.y = __float2bfloat16(y);
    return *reinterpret_cast<uint32_t*>(&t);
}
// packed fp32x2 FMA (PTX ISA sm_100+, base feature set)
#define FMA_F32X2(d, a, b, c)                                                  \
    asm("fma.rn.f32x2 %0, %1, %2, %3;"                                         \
        : "=l"(d) : "l"(a), "l"(b), "l"(c))

// ---------------------------------------------------------------------------
// K1: qkv = W x. q,k (o 0..127): single-pass bf16, both staged in one pass
//     (1 sync) then coalesced bf16 stores. v (o 128..191): 3-pass split,
//     fp16 out. 2 blocks/SM.
// Block = (b, n, pt of 128 px), 256 threads = 8 warps (2 px-rows x 4 o-cols).
// ---------------------------------------------------------------------------
#define XSH 0
#define XSL 17408
#define WSH 34816
#define WSL 62464
#define QSO 71680
#define SM_K1 (71680 + 2 * 18432)
#define XST 136
#define WST 72

__global__ __launch_bounds__(256, 2) void k1_mma(const float* __restrict__ x,
                                                 const float* __restrict__ Wm) {
    extern __shared__ char smem[];
    const uint32_t sbase = smem_u32(smem);
    const int tid = threadIdx.x, lane = tid & 31, wid = tid >> 5;
    const int wr = wid >> 2, wc = wid & 3;          // warp px-row (2), o-col (4)
    const int pt = blockIdx.x, n = blockIdx.y, b = blockIdx.z;

    // ---- load + split x tile: [64 c][128 px] fp32 -> xh/xl [c][px] bf16
    {
        const float4* xb4 = (const float4*)(x + (size_t)b * Cc * NA * HW
                                            + (size_t)n * HW + pt * 128);
        __nv_bfloat16* xh = (__nv_bfloat16*)(smem + XSH);
        __nv_bfloat16* xl = (__nv_bfloat16*)(smem + XSL);
#pragma unroll
        for (int i = 0; i < 8; i++) {
            int idx = tid + i * 256;                // 0..2047
            int c = idx >> 5, p4 = idx & 31;
            float4 v = xb4[(size_t)c * (NA * HW / 4) + p4];
            uint32_t h0 = packbf2(v.x, v.y), h1 = packbf2(v.z, v.w);
            float rx = v.x - __bfloat162float(((__nv_bfloat162*)&h0)->x);
            float ry = v.y - __bfloat162float(((__nv_bfloat162*)&h0)->y);
            float rz = v.z - __bfloat162float(((__nv_bfloat162*)&h1)->x);
            float rw = v.w - __bfloat162float(((__nv_bfloat162*)&h1)->y);
            uint32_t l0 = packbf2(rx, ry), l1 = packbf2(rz, rw);
            int e = c * XST + p4 * 4;
            *(uint2*)(xh + e) = make_uint2(h0, h1);
            *(uint2*)(xl + e) = make_uint2(l0, l1);
        }
        // ---- load + split W: hi all 192 rows; lo only v-rows (o>=128)
        const float4* wb4 = (const float4*)Wm;
        __nv_bfloat16* wh = (__nv_bfloat16*)(smem + WSH);
        __nv_bfloat16* wl = (__nv_bfloat16*)(smem + WSL);
#pragma unroll
        for (int i = 0; i < 12; i++) {
            int idx = tid + i * 256;                // 0..3071
            int o = idx >> 4, c4 = idx & 15;
            float4 v = wb4[idx];
            uint32_t h0 = packbf2(v.x, v.y), h1 = packbf2(v.z, v.w);
            *(uint2*)(wh + o * WST + c4 * 4) = make_uint2(h0, h1);
            if (o >= 128) {
                float rx = v.x - __bfloat162float(((__nv_bfloat162*)&h0)->x);
                float ry = v.y - __bfloat162float(((__nv_bfloat162*)&h0)->y);
                float rz = v.z - __bfloat162float(((__nv_bfloat162*)&h1)->x);
                float rw = v.w - __bfloat162float(((__nv_bfloat162*)&h1)->y);
                *(uint2*)(wl + (o - 128) * WST + c4 * 4)
                    = make_uint2(packbf2(rx, ry), packbf2(rz, rw));
            }
        }
    }
    __syncthreads();

    const int li = lane & 7, sel = lane >> 3;
    const int arow = ((sel & 2) ? 8 : 0) + li;      // k row in [k][m] tiles
    const int acol = (sel & 1) ? 8 : 0;             // m offset
    const int brow = arow;                          // n row in [n][k] tiles
    const int bkoff = acol;                         // k offset
    const int g = lane >> 2, t2 = (lane & 3) * 2;

    float acc[4][4][4];

    // ================= Phase A: q,k (o 0..127), single pass =================
#pragma unroll
    for (int mi = 0; mi < 4; mi++)
#pragma unroll
        for (int ni = 0; ni < 4; ni++)
#pragma unroll
            for (int e = 0; e < 4; e++) acc[mi][ni][e] = 0.0f;

#pragma unroll
    for (int kk = 0; kk < 4; kk++) {
        const int k0 = kk * 16;
        uint32_t a[4][4];
#pragma unroll
        for (int mi = 0; mi < 4; mi++)
            LDSM_X4_T(a[mi], sbase + XSH
                + (uint32_t)((k0 + arow) * XST + wr * 64 + mi * 16 + acol) * 2);
        uint32_t bf[2][4];
#pragma unroll
        for (int np = 0; np < 2; np++)
            LDSM_X4(bf[np], sbase + WSH
                + (uint32_t)((wc * 32 + np * 16 + brow) * WST + k0 + bkoff) * 2);
#pragma unroll
        for (int mi = 0; mi < 4; mi++)
#pragma unroll
            for (int ni = 0; ni < 4; ni++)
                mma16816(acc[mi][ni], a[mi],
                         bf[ni >> 1][(ni & 1) * 2], bf[ni >> 1][(ni & 1) * 2 + 1]);
    }

    // Epilogue A: stage BOTH q and k (disjoint halves), ONE sync, copy out
    {
        __nv_bfloat16* stg = (__nv_bfloat16*)(smem + QSO);  // [2][128][72]
        __nv_bfloat16* mystg = stg + (wc >> 1) * (128 * 72);
        const int obase = (wc & 1) * 32;
#pragma unroll
        for (int mi = 0; mi < 4; mi++) {
            const int px = wr * 64 + mi * 16 + g;
#pragma unroll
            for (int ni = 0; ni < 4; ni++) {
                const int o = obase + ni * 8 + t2;
                *(uint32_t*)(mystg + px * 72 + o)
                    = packbf2(acc[mi][ni][0], acc[mi][ni][1]);
                *(uint32_t*)(mystg + (px + 8) * 72 + o)
                    = packbf2(acc[mi][ni][2], acc[mi][ni][3]);
            }
        }
        __syncthreads();
        const size_t rowbase = (size_t)(b * 25 + n) * 4096 + pt * 128;
#pragma unroll
        for (int i = 0; i < 8; i++) {
            int idx = tid + i * 256;                // 0..2047
            int side = idx >> 10;                   // 0=q, 1=k
            int px = (idx >> 3) & 127, j = idx & 7;
            __nv_bfloat16* dst = side ? g_k : g_q;
            *(uint4*)(dst + (rowbase + px) * 64 + j * 8)
                = *(const uint4*)(stg + side * (128 * 72) + px * 72 + j * 8);
        }
    }

    // ================= Phase B: v (o 128..191), 3-pass split ================
#pragma unroll
    for (int mi = 0; mi < 4; mi++)
#pragma unroll
        for (int ni = 0; ni < 2; ni++)
#pragma unroll
            for (int e = 0; e < 4; e++) acc[mi][ni][e] = 0.0f;

#pragma unroll
    for (int kk = 0; kk < 4; kk++) {
        const int k0 = kk * 16;
        uint32_t ah[4][4], al[4][4];
#pragma unroll
        for (int mi = 0; mi < 4; mi++) {
            LDSM_X4_T(ah[mi], sbase + XSH
                + (uint32_t)((k0 + arow) * XST + wr * 64 + mi * 16 + acol) * 2);
            LDSM_X4_T(al[mi], sbase + XSL
                + (uint32_t)((k0 + arow) * XST + wr * 64 + mi * 16 + acol) * 2);
        }
        uint32_t bh[4], bl[4];
        LDSM_X4(bh, sbase + WSH
            + (uint32_t)((128 + wc * 16 + brow) * WST + k0 + bkoff) * 2);
        LDSM_X4(bl, sbase + WSL
            + (uint32_t)((wc * 16 + brow) * WST + k0 + bkoff) * 2);
#pragma unroll
        for (int mi = 0; mi < 4; mi++)
#pragma unroll
            for (int ni = 0; ni < 2; ni++) {
                mma16816(acc[mi][ni], ah[mi], bh[ni * 2], bh[ni * 2 + 1]);
                mma16816(acc[mi][ni], ah[mi], bl[ni * 2], bl[ni * 2 + 1]);
                mma16816(acc[mi][ni], al[mi], bh[ni * 2], bh[ni * 2 + 1]);
            }
    }

    // Epilogue B: stage v fp16 via smem (overlays xh region), coalesced out
    __syncthreads();
    __half* cssh = (__half*)smem;                   // [64][136] half = 17408B
#pragma unroll
    for (int mi = 0; mi < 4; mi++) {
        const int px = wr * 64 + mi * 16 + g;
#pragma unroll
        for (int ni = 0; ni < 2; ni++) {
            const int orel = wc * 16 + ni * 8 + t2;
            cssh[orel * 136 + px] = __float2half(acc[mi][ni][0]);
            cssh[(orel + 1) * 136 + px] = __float2half(acc[mi][ni][1]);
            cssh[orel * 136 + px + 8] = __float2half(acc[mi][ni][2]);
            cssh[(orel + 1) * 136 + px + 8] = __float2half(acc[mi][ni][3]);
        }
    }
    __syncthreads();
#pragma unroll
    for (int i = 0; i < 4; i++) {
        int idx = tid + i * 256;                    // 0..1023
        int orel = idx >> 4, j = idx & 15;          // 64 rows x 16 uint4 (128 half)
        *(uint4*)(g_v + ((size_t)(b * 64 + orel) * 25 + n) * 4096
                  + pt * 128 + j * 8)
            = *(const uint4*)(cssh + orel * 136 + j * 8);
    }
}

// ---------------------------------------------------------------------------
// K2: Gram via HMMA on bf16 q,k. Block = (chunk of 2048 f, b); 8 iterations
// of 256-f sub-chunks. Small smem (33KB) + launch_bounds(256,4) -> one wave.
// ---------------------------------------------------------------------------
#define GST 264
#define SM_GRAM (2 * 32 * GST * 2)

__global__ __launch_bounds__(256, 4) void k_gram() {
    extern __shared__ char gsm[];
    __nv_bfloat16* qs = (__nv_bfloat16*)gsm;        // [32][264]
    __nv_bfloat16* ks = qs + 32 * GST;
    const int ch8 = blockIdx.x, bb = blockIdx.y;
    const int tid = threadIdx.x, lane = tid & 31, w = tid >> 5;

    const int moff = (w & 1) * 16, noff = ((w >> 1) & 1) * 16;
    const int li = lane & 7, sel = lane >> 3;
    const uint32_t qb = smem_u32(qs), kb = smem_u32(ks);
    const uint32_t aoff = (uint32_t)((moff + ((sel & 1) ? 8 : 0) + li) * GST
                                     + ((sel & 2) ? 8 : 0)) * 2;
    const uint32_t boff = (uint32_t)((noff + ((sel & 2) ? 8 : 0) + li) * GST
                                     + ((sel & 1) ? 8 : 0)) * 2;

    float acc[2][4] = {{0, 0, 0, 0}, {0, 0, 0, 0}};
    float nacc[7];
#pragma unroll
    for (int i = 0; i < 7; i++) nacc[i] = 0.0f;

#pragma unroll 1
    for (int t = 0; t < 8; t++) {
        const int ch = ch8 * 8 + t;                 // 256-f sub-chunk index
        __syncthreads();
        for (int i = tid; i < 800; i += 256) {      // 25 rows x 32 uint4
            int nn = i >> 5, j = i & 31;
            ((uint4*)(qs + nn * GST))[j]
                = ((const uint4*)g_q)[(size_t)(bb * 25 + nn) * 32768 + (size_t)ch * 32 + j];
            ((uint4*)(ks + nn * GST))[j]
                = ((const uint4*)g_k)[(size_t)(bb * 25 + nn) * 32768 + (size_t)ch * 32 + j];
        }
        __syncthreads();

        // norms: warp w handles rows r = w, w+8, ... (<50); full-warp uint4
        {
            int cnt = 0;
            for (int r = w; r < 50; r += 8, cnt++) {
                const __nv_bfloat16* row = (r < 25) ? qs + r * GST
                                                    : ks + (r - 25) * GST;
                uint4 u = ((const uint4*)row)[lane];
                uint32_t vv[4] = {u.x, u.y, u.z, u.w};
                float s = 0.0f;
#pragma unroll
                for (int j = 0; j < 4; j++) {
                    __nv_bfloat162 h = *(__nv_bfloat162*)&vv[j];
                    float f0 = __bfloat162float(h.x), f1 = __bfloat162float(h.y);
                    s += f0 * f0 + f1 * f1;
                }
#pragma unroll
                for (int off = 16; off; off >>= 1)
                    s += __shfl_xor_sync(0xffffffffu, s, off);
                nacc[cnt] += s;
            }
        }

        if (w < 4) {
#pragma unroll 8
            for (int k0 = 0; k0 < 256; k0 += 16) {
                uint32_t a[4], bf[4];
                LDSM_X4(a, qb + aoff + k0 * 2);
                LDSM_X4(bf, kb + boff + k0 * 2);
                mma16816(acc[0], a, bf[0], bf[1]);
                mma16816(acc[1], a, bf[2], bf[3]);
            }
        }
    }

    float* gp = g_gp + (size_t)(bb * 128 + ch8) * 1088;
    if (lane == 0) {
        int cnt = 0;
        for (int r = w; r < 50; r += 8, cnt++) {
            int isk = r >= 25;
            gp[1024 + isk * 32 + (r - isk * 25)] = nacc[cnt];
        }
    }

    if (w < 4) {
        const int row = moff + (lane >> 2), col0 = noff + (lane & 3) * 2;
#pragma unroll
        for (int ni = 0; ni < 2; ni++) {
            const int col = col0 + ni * 8;
            gp[row * 32 + col] = acc[ni][0];
            gp[row * 32 + col + 1] = acc[ni][1];
            gp[(row + 8) * 32 + col] = acc[ni][2];
            gp[(row + 8) * 32 + col + 1] = acc[ni][3];
        }
    }
}

// ---------------------------------------------------------------------------
// K3: reduce 128 chunk-partials (fixed order, 4-acc ILP) + normalize +
// softmax. 1 block per b (single kernel -> one launch).
// ---------------------------------------------------------------------------
__global__ __launch_bounds__(704) void k_redsoft() {
    __shared__ float sS[675];
    const int b = blockIdx.x, tid = threadIdx.x;

    if (tid < 675) {
        int idx;
        if (tid < 625) idx = (tid / 25) * 32 + (tid % 25);
        else if (tid < 650) idx = 1024 + (tid - 625);
        else idx = 1056 + (tid - 650);
        const float* gp = g_gp + (size_t)b * 128 * 1088 + idx;
        float s0 = 0.f, s1 = 0.f, s2 = 0.f, s3 = 0.f;
#pragma unroll 8
        for (int ch = 0; ch < 128; ch += 4) {
            s0 += gp[(size_t)(ch + 0) * 1088];
            s1 += gp[(size_t)(ch + 1) * 1088];
            s2 += gp[(size_t)(ch + 2) * 1088];
            s3 += gp[(size_t)(ch + 3) * 1088];
        }
        sS[tid] = (s0 + s1) + (s2 + s3);
    }
    __syncthreads();

    if (tid < 25) {
        const int n = tid;
        float qn = fmaxf(sqrtf(fmaxf(sS[625 + n], 0.0f)), 1e-12f);
        float v[25];
        float mx = -3.0e38f;
#pragma unroll
        for (int m = 0; m < 25; m++) {
            float kn = fmaxf(sqrtf(fmaxf(sS[650 + m], 0.0f)), 1e-12f);
            v[m] = sS[n * 25 + m] / (qn * kn);
            mx = fmaxf(mx, v[m]);
        }
        float sum = 0.0f;
#pragma unroll
        for (int m = 0; m < 25; m++) {
            v[m] = expf(v[m] - mx);
            sum += v[m];
        }
        float inv = 1.0f / sum;
#pragma unroll
        for (int m = 0; m < 25; m++)
            g_att[(b * NA + n) * NA + m] = v[m] * inv;
    }
}

// ---------------------------------------------------------------------------
// K4: out[b,d,n,p] = sum_m att[b,n,m] * v[b,d,m,p].
// fp16 v from DRAM; fully-coalesced smem reads: thread owns u64 lanes
// col+32q (8B stride per warp -> 2 wavefronts per LDS.64, was 4).
// f32x2 FMA, 32 cols x 8 n-subsets, 4 blocks/SM.
// ---------------------------------------------------------------------------
#define SM_OUT (25 * 64 * 16 + 625 * 8)

__global__ __launch_bounds__(256, 4) void k_out(float* __restrict__ out) {
    extern __shared__ float osm[];
    float4* vs4 = (float4*)osm;                             // [25][64] float4
    unsigned long long* atts2 = (unsigned long long*)(osm + 25 * 256);  // [625]
    const int pt = blockIdx.x;                              // 0..15
    const int d  = blockIdx.y;                              // 0..63
    const int b  = blockIdx.z;                              // 0..3
    const int tid = threadIdx.x;
    const int col = tid & 31;                               // u64 lane base
    const int set = tid >> 5;                               // n-subset 0..7

    // n-subsets: {4,3,3,3,3,3,3,3}
    const int nstart = (set == 0) ? 0 : (4 + (set - 1) * 3);
    const int ncnt = (set == 0) ? 4 : 3;

    // load att packed {a,a}
    for (int i = tid; i < 625; i += 256) {
        float a = g_att[b * 625 + i];
        unsigned long long a2;
        asm("mov.b64 %0, {%1, %1};" : "=l"(a2) : "f"(a));
        atts2[i] = a2;
    }
    // load v tile: 25 rows x 256 px fp16 = 800 uint4 of half8, convert to fp32
    const uint4* vph = (const uint4*)(g_v + ((size_t)(b * 64 + d) * 25) * 4096);
#pragma unroll
    for (int i = tid; i < 800; i += 256) {
        int nn = i >> 5, j = i & 31;                        // 32 uint4 per row-tile
        uint4 u = vph[nn * 512 + pt * 32 + j];
        const __half2* h2 = (const __half2*)&u;
        float2 f0 = __half22float2(h2[0]), f1 = __half22float2(h2[1]);
        float2 f2 = __half22float2(h2[2]), f3 = __half22float2(h2[3]);
        vs4[nn * 64 + j * 2]     = make_float4(f0.x, f0.y, f1.x, f1.y);
        vs4[nn * 64 + j * 2 + 1] = make_float4(f2.x, f2.y, f3.x, f3.y);
    }
    __syncthreads();

    const unsigned long long* vs8 = (const unsigned long long*)vs4;  // [25][128] u64

    unsigned long long acc[4][4];                           // [n][q]: u64 idx col+32q
#pragma unroll
    for (int j = 0; j < 4; j++)
#pragma unroll
        for (int e = 0; e < 4; e++) acc[j][e] = 0ULL;

#pragma unroll
    for (int m = 0; m < 25; m++) {
        unsigned long long v0 = vs8[m * 128 + col];
        unsigned long long v1 = vs8[m * 128 + 32 + col];
        unsigned long long v2 = vs8[m * 128 + 64 + col];
        unsigned long long v3 = vs8[m * 128 + 96 + col];
#pragma unroll
        for (int j = 0; j < 4; j++) {
            if (j < ncnt) {
                unsigned long long a2 = atts2[(nstart + j) * 25 + m];
                FMA_F32X2(acc[j][0], a2, v0, acc[j][0]);
                FMA_F32X2(acc[j][1], a2, v1, acc[j][1]);
                FMA_F32X2(acc[j][2], a2, v2, acc[j][2]);
                FMA_F32X2(acc[j][3], a2, v3, acc[j][3]);
            }
        }
    }

    float* ob = out + ((size_t)(b * 64 + d) * 25) * 4096 + pt * 256;
#pragma unroll
    for (int j = 0; j < 4; j++) {
        if (j < ncnt) {
            const int n = nstart + j;
#pragma unroll
            for (int q = 0; q < 4; q++)
                *(float2*)(ob + (size_t)n * 4096 + 2 * (col + 32 * q))
                    = *(float2*)&acc[j][q];
        }
    }
}

// ---------------------------------------------------------------------------
extern "C" void kernel_launch(void* const* d_in, const int* in_sizes, int n_in,
                              void* d_out, int out_size) {
    const float* x  = (const float*)d_in[0];
    const float* Wm = (const float*)d_in[1];
    float* out = (float*)d_out;

    cudaFuncSetAttribute(k1_mma, cudaFuncAttributeMaxDynamicSharedMemorySize, SM_K1);
    cudaFuncSetAttribute(k_gram, cudaFuncAttributeMaxDynamicSharedMemorySize, SM_GRAM);
    cudaFuncSetAttribute(k_out, cudaFuncAttributeMaxDynamicSharedMemorySize, SM_OUT);

    k1_mma<<<dim3(32, 25, 4), 256, SM_K1>>>(x, Wm);
    k_gram<<<dim3(128, 4), 256, SM_GRAM>>>();
    k_redsoft<<<4, 704>>>();
    k_out<<<dim3(16, 64, 4), 256, SM_OUT>>>(out);
}

// round 15
// speedup vs baseline: 1.0560x; 1.0560x over previous
#include <cuda_runtime.h>
#include <cuda_bf16.h>
#include <cuda_fp16.h>
#include <cstdint>

// Problem constants
#define Bb 4
#define Cc 64
#define NA 25
#define HW 4096
#define Dd 64
#define Oo 192

// ---------------------------------------------------------------------------
// Scratch (device globals -- no runtime allocation allowed)
// ---------------------------------------------------------------------------
__device__ __nv_bfloat16 g_q[(size_t)Bb * NA * HW * Dd];   // [b][n][px][d] 52MB
__device__ __nv_bfloat16 g_k[(size_t)Bb * NA * HW * Dd];   // 52MB
__device__ __half g_v[(size_t)Bb * Dd * NA * HW];          // [b][d][n][px] 52MB fp16
__device__ float g_gp[(size_t)Bb * 128 * 1088];            // per-(b,chunk): S 32x32 + qn2 + kn2
__device__ float g_att[Bb * NA * NA];

// ---------------------------------------------------------------------------
// Helpers: ldmatrix + mma.sync (plain sm_80+ PTX -- compiles on compute_103)
// ---------------------------------------------------------------------------
__device__ __forceinline__ uint32_t smem_u32(const void* p) {
    uint32_t a;
    asm("{ .reg .u64 t; cvta.to.shared.u64 t, %1; cvt.u32.u64 %0, t; }" : "=r"(a) : "l"(p));
    return a;
}
#define LDSM_X4(r, addr)                                                       \
    asm volatile("ldmatrix.sync.aligned.m8n8.x4.shared.b16 {%0,%1,%2,%3}, [%4];" \
                 : "=r"((r)[0]), "=r"((r)[1]), "=r"((r)[2]), "=r"((r)[3])      \
                 : "r"(addr))
#define LDSM_X4_T(r, addr)                                                     \
    asm volatile("ldmatrix.sync.aligned.m8n8.x4.trans.shared.b16 {%0,%1,%2,%3}, [%4];" \
                 : "=r"((r)[0]), "=r"((r)[1]), "=r"((r)[2]), "=r"((r)[3])      \
                 : "r"(addr))
__device__ __forceinline__ void mma16816(float* c, const uint32_t* a,
                                         uint32_t b0, uint32_t b1) {
    asm volatile(
        "mma.sync.aligned.m16n8k16.row.col.f32.bf16.bf16.f32 "
        "{%0,%1,%2,%3}, {%4,%5,%6,%7}, {%8,%9}, {%0,%1,%2,%3};"
        : "+f"(c[0]), "+f"(c[1]), "+f"(c[2]), "+f"(c[3])
        : "r"(a[0]), "r"(a[1]), "r"(a[2]), "r"(a[3]), "r"(b0), "r"(b1));
}
__device__ __forceinline__ uint32_t packbf2(float x, float y) {
    __nv_bfloat162 t;
    t.x = __float2bfloat16(x);
    t.y = __float2bfloat16(y);
    return *reinterpret_cast<uint32_t*>(&t);
}
// packed fp32x2 FMA (PTX ISA sm_100+, base feature set)
#define FMA_F32X2(d, a, b, c)                                                  \
    asm("fma.rn.f32x2 %0, %1, %2, %3;"                                         \
        : "=l"(d) : "l"(a), "l"(b), "l"(c))

// ---------------------------------------------------------------------------
// K1: qkv = W x. q,k (o 0..127): single-pass bf16, staged coalesced bf16 out
//     (two-pass staging, R13 config). v (o 128..191): 3-pass split, fp16 out.
// Block = (b, n, pt of 128 px), 256 threads = 8 warps (2 px-rows x 4 o-cols).
// ---------------------------------------------------------------------------
#define XSH 0
#define XSL 17408
#define WSH 34816
#define WSL 62464
#define QSO 71680
#define SM_K1 90112
#define XST 136
#define WST 72

__global__ __launch_bounds__(256, 2) void k1_mma(const float* __restrict__ x,
                                                 const float* __restrict__ Wm) {
    extern __shared__ char smem[];
    const uint32_t sbase = smem_u32(smem);
    const int tid = threadIdx.x, lane = tid & 31, wid = tid >> 5;
    const int wr = wid >> 2, wc = wid & 3;          // warp px-row (2), o-col (4)
    const int pt = blockIdx.x, n = blockIdx.y, b = blockIdx.z;

    // ---- load + split x tile: [64 c][128 px] fp32 -> xh/xl [c][px] bf16
    {
        const float4* xb4 = (const float4*)(x + (size_t)b * Cc * NA * HW
                                            + (size_t)n * HW + pt * 128);
        __nv_bfloat16* xh = (__nv_bfloat16*)(smem + XSH);
        __nv_bfloat16* xl = (__nv_bfloat16*)(smem + XSL);
#pragma unroll
        for (int i = 0; i < 8; i++) {
            int idx = tid + i * 256;                // 0..2047
            int c = idx >> 5, p4 = idx & 31;
            float4 v = xb4[(size_t)c * (NA * HW / 4) + p4];
            uint32_t h0 = packbf2(v.x, v.y), h1 = packbf2(v.z, v.w);
            float rx = v.x - __bfloat162float(((__nv_bfloat162*)&h0)->x);
            float ry = v.y - __bfloat162float(((__nv_bfloat162*)&h0)->y);
            float rz = v.z - __bfloat162float(((__nv_bfloat162*)&h1)->x);
            float rw = v.w - __bfloat162float(((__nv_bfloat162*)&h1)->y);
            uint32_t l0 = packbf2(rx, ry), l1 = packbf2(rz, rw);
            int e = c * XST + p4 * 4;
            *(uint2*)(xh + e) = make_uint2(h0, h1);
            *(uint2*)(xl + e) = make_uint2(l0, l1);
        }
        // ---- load + split W: hi all 192 rows; lo only v-rows (o>=128)
        const float4* wb4 = (const float4*)Wm;
        __nv_bfloat16* wh = (__nv_bfloat16*)(smem + WSH);
        __nv_bfloat16* wl = (__nv_bfloat16*)(smem + WSL);
#pragma unroll
        for (int i = 0; i < 12; i++) {
            int idx = tid + i * 256;                // 0..3071
            int o = idx >> 4, c4 = idx & 15;
            float4 v = wb4[idx];
            uint32_t h0 = packbf2(v.x, v.y), h1 = packbf2(v.z, v.w);
            *(uint2*)(wh + o * WST + c4 * 4) = make_uint2(h0, h1);
            if (o >= 128) {
                float rx = v.x - __bfloat162float(((__nv_bfloat162*)&h0)->x);
                float ry = v.y - __bfloat162float(((__nv_bfloat162*)&h0)->y);
                float rz = v.z - __bfloat162float(((__nv_bfloat162*)&h1)->x);
                float rw = v.w - __bfloat162float(((__nv_bfloat162*)&h1)->y);
                *(uint2*)(wl + (o - 128) * WST + c4 * 4)
                    = make_uint2(packbf2(rx, ry), packbf2(rz, rw));
            }
        }
    }
    __syncthreads();

    const int li = lane & 7, sel = lane >> 3;
    const int arow = ((sel & 2) ? 8 : 0) + li;      // k row in [k][m] tiles
    const int acol = (sel & 1) ? 8 : 0;             // m offset
    const int brow = arow;                          // n row in [n][k] tiles
    const int bkoff = acol;                         // k offset
    const int g = lane >> 2, t2 = (lane & 3) * 2;

    float acc[4][4][4];

    // ================= Phase A: q,k (o 0..127), single pass =================
#pragma unroll
    for (int mi = 0; mi < 4; mi++)
#pragma unroll
        for (int ni = 0; ni < 4; ni++)
#pragma unroll
            for (int e = 0; e < 4; e++) acc[mi][ni][e] = 0.0f;

#pragma unroll
    for (int kk = 0; kk < 4; kk++) {
        const int k0 = kk * 16;
        uint32_t a[4][4];
#pragma unroll
        for (int mi = 0; mi < 4; mi++)
            LDSM_X4_T(a[mi], sbase + XSH
                + (uint32_t)((k0 + arow) * XST + wr * 64 + mi * 16 + acol) * 2);
        uint32_t bf[2][4];
#pragma unroll
        for (int np = 0; np < 2; np++)
            LDSM_X4(bf[np], sbase + WSH
                + (uint32_t)((wc * 32 + np * 16 + brow) * WST + k0 + bkoff) * 2);
#pragma unroll
        for (int mi = 0; mi < 4; mi++)
#pragma unroll
            for (int ni = 0; ni < 4; ni++)
                mma16816(acc[mi][ni], a[mi],
                         bf[ni >> 1][(ni & 1) * 2], bf[ni >> 1][(ni & 1) * 2 + 1]);
    }

    // Epilogue A: stage q then k through padded smem, coalesced bf16 stores
    {
        __nv_bfloat16* qsb = (__nv_bfloat16*)(smem + QSO);
        const size_t rowbase = (size_t)(b * 25 + n) * 4096 + pt * 128;
#pragma unroll 1
        for (int side = 0; side < 2; side++) {
            __syncthreads();
            if ((wc >> 1) == side) {                // wc 0,1 -> q; wc 2,3 -> k
                const int obase = (wc & 1) * 32;
#pragma unroll
                for (int mi = 0; mi < 4; mi++) {
                    const int px = wr * 64 + mi * 16 + g;
#pragma unroll
                    for (int ni = 0; ni < 4; ni++) {
                        const int o = obase + ni * 8 + t2;
                        *(uint32_t*)(qsb + px * 72 + o)
                            = packbf2(acc[mi][ni][0], acc[mi][ni][1]);
                        *(uint32_t*)(qsb + (px + 8) * 72 + o)
                            = packbf2(acc[mi][ni][2], acc[mi][ni][3]);
                    }
                }
            }
            __syncthreads();
            __nv_bfloat16* dst = side ? g_k : g_q;
#pragma unroll
            for (int i = 0; i < 4; i++) {
                int idx = tid + i * 256;            // 0..1023
                int px = idx >> 3, j = idx & 7;
                *(uint4*)(dst + (rowbase + px) * 64 + j * 8)
                    = *(const uint4*)(qsb + px * 72 + j * 8);
            }
        }
    }

    // ================= Phase B: v (o 128..191), 3-pass split ================
#pragma unroll
    for (int mi = 0; mi < 4; mi++)
#pragma unroll
        for (int ni = 0; ni < 2; ni++)
#pragma unroll
            for (int e = 0; e < 4; e++) acc[mi][ni][e] = 0.0f;

#pragma unroll
    for (int kk = 0; kk < 4; kk++) {
        const int k0 = kk * 16;
        uint32_t ah[4][4], al[4][4];
#pragma unroll
        for (int mi = 0; mi < 4; mi++) {
            LDSM_X4_T(ah[mi], sbase + XSH
                + (uint32_t)((k0 + arow) * XST + wr * 64 + mi * 16 + acol) * 2);
            LDSM_X4_T(al[mi], sbase + XSL
                + (uint32_t)((k0 + arow) * XST + wr * 64 + mi * 16 + acol) * 2);
        }
        uint32_t bh[4], bl[4];
        LDSM_X4(bh, sbase + WSH
            + (uint32_t)((128 + wc * 16 + brow) * WST + k0 + bkoff) * 2);
        LDSM_X4(bl, sbase + WSL
            + (uint32_t)((wc * 16 + brow) * WST + k0 + bkoff) * 2);
#pragma unroll
        for (int mi = 0; mi < 4; mi++)
#pragma unroll
            for (int ni = 0; ni < 2; ni++) {
                mma16816(acc[mi][ni], ah[mi], bh[ni * 2], bh[ni * 2 + 1]);
                mma16816(acc[mi][ni], ah[mi], bl[ni * 2], bl[ni * 2 + 1]);
                mma16816(acc[mi][ni], al[mi], bh[ni * 2], bh[ni * 2 + 1]);
            }
    }

    // Epilogue B: stage v fp16 via smem (overlays xh region), coalesced out
    __syncthreads();
    __half* cssh = (__half*)smem;                   // [64][136] half = 17408B
#pragma unroll
    for (int mi = 0; mi < 4; mi++) {
        const int px = wr * 64 + mi * 16 + g;
#pragma unroll
        for (int ni = 0; ni < 2; ni++) {
            const int orel = wc * 16 + ni * 8 + t2;
            cssh[orel * 136 + px] = __float2half(acc[mi][ni][0]);
            cssh[(orel + 1) * 136 + px] = __float2half(acc[mi][ni][1]);
            cssh[orel * 136 + px + 8] = __float2half(acc[mi][ni][2]);
            cssh[(orel + 1) * 136 + px + 8] = __float2half(acc[mi][ni][3]);
        }
    }
    __syncthreads();
#pragma unroll
    for (int i = 0; i < 4; i++) {
        int idx = tid + i * 256;                    // 0..1023
        int orel = idx >> 4, j = idx & 15;          // 64 rows x 16 uint4 (128 half)
        *(uint4*)(g_v + ((size_t)(b * 64 + orel) * 25 + n) * 4096
                  + pt * 128 + j * 8)
            = *(const uint4*)(cssh + orel * 136 + j * 8);
    }
}

// ---------------------------------------------------------------------------
// K2: Gram via HMMA on bf16 q,k. Block = (chunk of 2048 f, b); 8 iterations
// of 256-f sub-chunks. Small smem (33KB) + launch_bounds(256,4) -> one wave.
// ---------------------------------------------------------------------------
#define GST 264
#define SM_GRAM (2 * 32 * GST * 2)

__global__ __launch_bounds__(256, 4) void k_gram() {
    extern __shared__ char gsm[];
    __nv_bfloat16* qs = (__nv_bfloat16*)gsm;        // [32][264]
    __nv_bfloat16* ks = qs + 32 * GST;
    const int ch8 = blockIdx.x, bb = blockIdx.y;
    const int tid = threadIdx.x, lane = tid & 31, w = tid >> 5;

    const int moff = (w & 1) * 16, noff = ((w >> 1) & 1) * 16;
    const int li = lane & 7, sel = lane >> 3;
    const uint32_t qb = smem_u32(qs), kb = smem_u32(ks);
    const uint32_t aoff = (uint32_t)((moff + ((sel & 1) ? 8 : 0) + li) * GST
                                     + ((sel & 2) ? 8 : 0)) * 2;
    const uint32_t boff = (uint32_t)((noff + ((sel & 2) ? 8 : 0) + li) * GST
                                     + ((sel & 1) ? 8 : 0)) * 2;

    float acc[2][4] = {{0, 0, 0, 0}, {0, 0, 0, 0}};
    float nacc[7];
#pragma unroll
    for (int i = 0; i < 7; i++) nacc[i] = 0.0f;

#pragma unroll 1
    for (int t = 0; t < 8; t++) {
        const int ch = ch8 * 8 + t;                 // 256-f sub-chunk index
        __syncthreads();
        for (int i = tid; i < 800; i += 256) {      // 25 rows x 32 uint4
            int nn = i >> 5, j = i & 31;
            ((uint4*)(qs + nn * GST))[j]
                = ((const uint4*)g_q)[(size_t)(bb * 25 + nn) * 32768 + (size_t)ch * 32 + j];
            ((uint4*)(ks + nn * GST))[j]
                = ((const uint4*)g_k)[(size_t)(bb * 25 + nn) * 32768 + (size_t)ch * 32 + j];
        }
        __syncthreads();

        // norms: warp w handles rows r = w, w+8, ... (<50); full-warp uint4
        {
            int cnt = 0;
            for (int r = w; r < 50; r += 8, cnt++) {
                const __nv_bfloat16* row = (r < 25) ? qs + r * GST
                                                    : ks + (r - 25) * GST;
                uint4 u = ((const uint4*)row)[lane];
                uint32_t vv[4] = {u.x, u.y, u.z, u.w};
                float s = 0.0f;
#pragma unroll
                for (int j = 0; j < 4; j++) {
                    __nv_bfloat162 h = *(__nv_bfloat162*)&vv[j];
                    float f0 = __bfloat162float(h.x), f1 = __bfloat162float(h.y);
                    s += f0 * f0 + f1 * f1;
                }
#pragma unroll
                for (int off = 16; off; off >>= 1)
                    s += __shfl_xor_sync(0xffffffffu, s, off);
                nacc[cnt] += s;
            }
        }

        if (w < 4) {
#pragma unroll 8
            for (int k0 = 0; k0 < 256; k0 += 16) {
                uint32_t a[4], bf[4];
                LDSM_X4(a, qb + aoff + k0 * 2);
                LDSM_X4(bf, kb + boff + k0 * 2);
                mma16816(acc[0], a, bf[0], bf[1]);
                mma16816(acc[1], a, bf[2], bf[3]);
            }
        }
    }

    float* gp = g_gp + (size_t)(bb * 128 + ch8) * 1088;
    if (lane == 0) {
        int cnt = 0;
        for (int r = w; r < 50; r += 8, cnt++) {
            int isk = r >= 25;
            gp[1024 + isk * 32 + (r - isk * 25)] = nacc[cnt];
        }
    }

    if (w < 4) {
        const int row = moff + (lane >> 2), col0 = noff + (lane & 3) * 2;
#pragma unroll
        for (int ni = 0; ni < 2; ni++) {
            const int col = col0 + ni * 8;
            gp[row * 32 + col] = acc[ni][0];
            gp[row * 32 + col + 1] = acc[ni][1];
            gp[(row + 8) * 32 + col] = acc[ni][2];
            gp[(row + 8) * 32 + col + 1] = acc[ni][3];
        }
    }
}

// ---------------------------------------------------------------------------
// K3: reduce 128 chunk-partials (fixed order, 4-acc ILP) + normalize +
// softmax. 1 block per b (single kernel -> one launch).
// ---------------------------------------------------------------------------
__global__ __launch_bounds__(704) void k_redsoft() {
    __shared__ float sS[675];
    const int b = blockIdx.x, tid = threadIdx.x;

    if (tid < 675) {
        int idx;
        if (tid < 625) idx = (tid / 25) * 32 + (tid % 25);
        else if (tid < 650) idx = 1024 + (tid - 625);
        else idx = 1056 + (tid - 650);
        const float* gp = g_gp + (size_t)b * 128 * 1088 + idx;
        float s0 = 0.f, s1 = 0.f, s2 = 0.f, s3 = 0.f;
#pragma unroll 8
        for (int ch = 0; ch < 128; ch += 4) {
            s0 += gp[(size_t)(ch + 0) * 1088];
            s1 += gp[(size_t)(ch + 1) * 1088];
            s2 += gp[(size_t)(ch + 2) * 1088];
            s3 += gp[(size_t)(ch + 3) * 1088];
        }
        sS[tid] = (s0 + s1) + (s2 + s3);
    }
    __syncthreads();

    if (tid < 25) {
        const int n = tid;
        float qn = fmaxf(sqrtf(fmaxf(sS[625 + n], 0.0f)), 1e-12f);
        float v[25];
        float mx = -3.0e38f;
#pragma unroll
        for (int m = 0; m < 25; m++) {
            float kn = fmaxf(sqrtf(fmaxf(sS[650 + m], 0.0f)), 1e-12f);
            v[m] = sS[n * 25 + m] / (qn * kn);
            mx = fmaxf(mx, v[m]);
        }
        float sum = 0.0f;
#pragma unroll
        for (int m = 0; m < 25; m++) {
            v[m] = expf(v[m] - mx);
            sum += v[m];
        }
        float inv = 1.0f / sum;
#pragma unroll
        for (int m = 0; m < 25; m++)
            g_att[(b * NA + n) * NA + m] = v[m] * inv;
    }
}

// ---------------------------------------------------------------------------
// K4: out[b,d,n,p] = sum_m att[b,n,m] * v[b,d,m,p].
// 128 threads per block = half the smem re-readers per tile (each thread
// covers 6-7 n outputs) -> v-LDS wavefronts per tile halved. f32x2 FMA.
// ---------------------------------------------------------------------------
#define SM_OUT (25 * 64 * 16 + 625 * 8)

__global__ __launch_bounds__(128, 4) void k_out(float* __restrict__ out) {
    extern __shared__ float osm[];
    float4* vs4 = (float4*)osm;                             // [25][64] float4
    unsigned long long* atts2 = (unsigned long long*)(osm + 25 * 256);  // [625]
    const int pt = blockIdx.x;                              // 0..15
    const int d  = blockIdx.y;                              // 0..63
    const int b  = blockIdx.z;                              // 0..3
    const int tid = threadIdx.x;
    const int col = tid & 31;                               // u64 lane base
    const int set = tid >> 5;                               // n-subset 0..3

    // n-subsets: {7,6,6,6}
    const int nstart = (set == 0) ? 0 : (7 + (set - 1) * 6);
    const int ncnt = (set == 0) ? 7 : 6;

    // load att packed {a,a}
    for (int i = tid; i < 625; i += 128) {
        float a = g_att[b * 625 + i];
        unsigned long long a2;
        asm("mov.b64 %0, {%1, %1};" : "=l"(a2) : "f"(a));
        atts2[i] = a2;
    }
    // load v tile: 25 rows x 256 px fp16 = 800 uint4 of half8, convert to fp32
    const uint4* vph = (const uint4*)(g_v + ((size_t)(b * 64 + d) * 25) * 4096);
#pragma unroll
    for (int i = tid; i < 800; i += 128) {
        int nn = i >> 5, j = i & 31;                        // 32 uint4 per row-tile
        uint4 u = vph[nn * 512 + pt * 32 + j];
        const __half2* h2 = (const __half2*)&u;
        float2 f0 = __half22float2(h2[0]), f1 = __half22float2(h2[1]);
        float2 f2 = __half22float2(h2[2]), f3 = __half22float2(h2[3]);
        vs4[nn * 64 + j * 2]     = make_float4(f0.x, f0.y, f1.x, f1.y);
        vs4[nn * 64 + j * 2 + 1] = make_float4(f2.x, f2.y, f3.x, f3.y);
    }
    __syncthreads();

    const unsigned long long* vs8 = (const unsigned long long*)vs4;  // [25][128] u64

    unsigned long long acc[7][4];                           // [n][q]: u64 idx col+32q
#pragma unroll
    for (int j = 0; j < 7; j++)
#pragma unroll
        for (int e = 0; e < 4; e++) acc[j][e] = 0ULL;

#pragma unroll
    for (int m = 0; m < 25; m++) {
        unsigned long long v0 = vs8[m * 128 + col];
        unsigned long long v1 = vs8[m * 128 + 32 + col];
        unsigned long long v2 = vs8[m * 128 + 64 + col];
        unsigned long long v3 = vs8[m * 128 + 96 + col];
#pragma unroll
        for (int j = 0; j < 7; j++) {
            if (j < ncnt) {
                unsigned long long a2 = atts2[(nstart + j) * 25 + m];
                FMA_F32X2(acc[j][0], a2, v0, acc[j][0]);
                FMA_F32X2(acc[j][1], a2, v1, acc[j][1]);
                FMA_F32X2(acc[j][2], a2, v2, acc[j][2]);
                FMA_F32X2(acc[j][3], a2, v3, acc[j][3]);
            }
        }
    }

    float* ob = out + ((size_t)(b * 64 + d) * 25) * 4096 + pt * 256;
#pragma unroll
    for (int j = 0; j < 7; j++) {
        if (j < ncnt) {
            const int n = nstart + j;
#pragma unroll
            for (int q = 0; q < 4; q++)
                *(float2*)(ob + (size_t)n * 4096 + 2 * (col + 32 * q))
                    = *(float2*)&acc[j][q];
        }
    }
}

// ---------------------------------------------------------------------------
extern "C" void kernel_launch(void* const* d_in, const int* in_sizes, int n_in,
                              void* d_out, int out_size) {
    const float* x  = (const float*)d_in[0];
    const float* Wm = (const float*)d_in[1];
    float* out = (float*)d_out;

    cudaFuncSetAttribute(k1_mma, cudaFuncAttributeMaxDynamicSharedMemorySize, SM_K1);
    cudaFuncSetAttribute(k_gram, cudaFuncAttributeMaxDynamicSharedMemorySize, SM_GRAM);
    cudaFuncSetAttribute(k_out, cudaFuncAttributeMaxDynamicSharedMemorySize, SM_OUT);

    k1_mma<<<dim3(32, 25, 4), 256, SM_K1>>>(x, Wm);
    k_gram<<<dim3(128, 4), 256, SM_GRAM>>>();
    k_redsoft<<<4, 704>>>();
    k_out<<<dim3(16, 64, 4), 128, SM_OUT>>>(out);
}

// round 16
// speedup vs baseline: 1.1408x; 1.0803x over previous
#include <cuda_runtime.h>
#include <cuda_bf16.h>
#include <cuda_fp16.h>
#include <cstdint>

// Problem constants
#define Bb 4
#define Cc 64
#define NA 25
#define HW 4096
#define Dd 64
#define Oo 192

// ---------------------------------------------------------------------------
// Scratch (device globals -- no runtime allocation allowed)
// q/k rows use a PERMUTED feature layout (warp-coalesced fragment order);
// gram only needs a consistent bijection, which this is.
// ---------------------------------------------------------------------------
__device__ __nv_bfloat16 g_q[(size_t)Bb * NA * HW * Dd];   // [b][n][262144 perm] 52MB
__device__ __nv_bfloat16 g_k[(size_t)Bb * NA * HW * Dd];   // 52MB
__device__ __half g_v[(size_t)Bb * Dd * NA * HW];          // [b][d][n][px] 52MB fp16
__device__ float g_gp[(size_t)Bb * 128 * 1088];            // per-(b,chunk): S 32x32 + qn2 + kn2
__device__ float g_att[Bb * NA * NA];

// ---------------------------------------------------------------------------
// Helpers: ldmatrix + mma.sync (plain sm_80+ PTX -- compiles on compute_103)
// ---------------------------------------------------------------------------
__device__ __forceinline__ uint32_t smem_u32(const void* p) {
    uint32_t a;
    asm("{ .reg .u64 t; cvta.to.shared.u64 t, %1; cvt.u32.u64 %0, t; }" : "=r"(a) : "l"(p));
    return a;
}
#define LDSM_X4(r, addr)                                                       \
    asm volatile("ldmatrix.sync.aligned.m8n8.x4.shared.b16 {%0,%1,%2,%3}, [%4];" \
                 : "=r"((r)[0]), "=r"((r)[1]), "=r"((r)[2]), "=r"((r)[3])      \
                 : "r"(addr))
#define LDSM_X4_T(r, addr)                                                     \
    asm volatile("ldmatrix.sync.aligned.m8n8.x4.trans.shared.b16 {%0,%1,%2,%3}, [%4];" \
                 : "=r"((r)[0]), "=r"((r)[1]), "=r"((r)[2]), "=r"((r)[3])      \
                 : "r"(addr))
__device__ __forceinline__ void mma16816(float* c, const uint32_t* a,
                                         uint32_t b0, uint32_t b1) {
    asm volatile(
        "mma.sync.aligned.m16n8k16.row.col.f32.bf16.bf16.f32 "
        "{%0,%1,%2,%3}, {%4,%5,%6,%7}, {%8,%9}, {%0,%1,%2,%3};"
        : "+f"(c[0]), "+f"(c[1]), "+f"(c[2]), "+f"(c[3])
        : "r"(a[0]), "r"(a[1]), "r"(a[2]), "r"(a[3]), "r"(b0), "r"(b1));
}
__device__ __forceinline__ uint32_t packbf2(float x, float y) {
    __nv_bfloat162 t;
    t.x = __float2bfloat16(x);
    t.y = __float2bfloat16(y);
    return *reinterpret_cast<uint32_t*>(&t);
}
// packed fp32x2 FMA (PTX ISA sm_100+, base feature set)
#define FMA_F32X2(d, a, b, c)                                                  \
    asm("fma.rn.f32x2 %0, %1, %2, %3;"                                         \
        : "=l"(d) : "l"(a), "l"(b), "l"(c))

// ---------------------------------------------------------------------------
// K1: qkv = W x. q,k (o 0..127): single-pass bf16, DIRECT warp-coalesced
//     fragment stores (permuted layout, no staging, no syncs).
//     v (o 128..191): 3-pass split, fp16 out. 2 blocks/SM.
// Block = (b, n, pt of 128 px), 256 threads = 8 warps (2 px-rows x 4 o-cols).
// ---------------------------------------------------------------------------
#define XSH 0
#define XSL 17408
#define WSH 34816
#define WSL 62464
#define SM_K1 71680
#define XST 136
#define WST 72

__global__ __launch_bounds__(256, 2) void k1_mma(const float* __restrict__ x,
                                                 const float* __restrict__ Wm) {
    extern __shared__ char smem[];
    const uint32_t sbase = smem_u32(smem);
    const int tid = threadIdx.x, lane = tid & 31, wid = tid >> 5;
    const int wr = wid >> 2, wc = wid & 3;          // warp px-row (2), o-col (4)
    const int pt = blockIdx.x, n = blockIdx.y, b = blockIdx.z;

    // ---- load + split x tile: [64 c][128 px] fp32 -> xh/xl [c][px] bf16
    {
        const float4* xb4 = (const float4*)(x + (size_t)b * Cc * NA * HW
                                            + (size_t)n * HW + pt * 128);
        __nv_bfloat16* xh = (__nv_bfloat16*)(smem + XSH);
        __nv_bfloat16* xl = (__nv_bfloat16*)(smem + XSL);
#pragma unroll
        for (int i = 0; i < 8; i++) {
            int idx = tid + i * 256;                // 0..2047
            int c = idx >> 5, p4 = idx & 31;
            float4 v = xb4[(size_t)c * (NA * HW / 4) + p4];
            uint32_t h0 = packbf2(v.x, v.y), h1 = packbf2(v.z, v.w);
            float rx = v.x - __bfloat162float(((__nv_bfloat162*)&h0)->x);
            float ry = v.y - __bfloat162float(((__nv_bfloat162*)&h0)->y);
            float rz = v.z - __bfloat162float(((__nv_bfloat162*)&h1)->x);
            float rw = v.w - __bfloat162float(((__nv_bfloat162*)&h1)->y);
            uint32_t l0 = packbf2(rx, ry), l1 = packbf2(rz, rw);
            int e = c * XST + p4 * 4;
            *(uint2*)(xh + e) = make_uint2(h0, h1);
            *(uint2*)(xl + e) = make_uint2(l0, l1);
        }
        // ---- load + split W: hi all 192 rows; lo only v-rows (o>=128)
        const float4* wb4 = (const float4*)Wm;
        __nv_bfloat16* wh = (__nv_bfloat16*)(smem + WSH);
        __nv_bfloat16* wl = (__nv_bfloat16*)(smem + WSL);
#pragma unroll
        for (int i = 0; i < 12; i++) {
            int idx = tid + i * 256;                // 0..3071
            int o = idx >> 4, c4 = idx & 15;
            float4 v = wb4[idx];
            uint32_t h0 = packbf2(v.x, v.y), h1 = packbf2(v.z, v.w);
            *(uint2*)(wh + o * WST + c4 * 4) = make_uint2(h0, h1);
            if (o >= 128) {
                float rx = v.x - __bfloat162float(((__nv_bfloat162*)&h0)->x);
                float ry = v.y - __bfloat162float(((__nv_bfloat162*)&h0)->y);
                float rz = v.z - __bfloat162float(((__nv_bfloat162*)&h1)->x);
                float rw = v.w - __bfloat162float(((__nv_bfloat162*)&h1)->y);
                *(uint2*)(wl + (o - 128) * WST + c4 * 4)
                    = make_uint2(packbf2(rx, ry), packbf2(rz, rw));
            }
        }
    }
    __syncthreads();

    const int li = lane & 7, sel = lane >> 3;
    const int arow = ((sel & 2) ? 8 : 0) + li;      // k row in [k][m] tiles
    const int acol = (sel & 1) ? 8 : 0;             // m offset
    const int brow = arow;                          // n row in [n][k] tiles
    const int bkoff = acol;                         // k offset
    const int g = lane >> 2, t2 = (lane & 3) * 2;

    float acc[4][4][4];

    // ================= Phase A: q,k (o 0..127), single pass =================
#pragma unroll
    for (int mi = 0; mi < 4; mi++)
#pragma unroll
        for (int ni = 0; ni < 4; ni++)
#pragma unroll
            for (int e = 0; e < 4; e++) acc[mi][ni][e] = 0.0f;

#pragma unroll
    for (int kk = 0; kk < 4; kk++) {
        const int k0 = kk * 16;
        uint32_t a[4][4];
#pragma unroll
        for (int mi = 0; mi < 4; mi++)
            LDSM_X4_T(a[mi], sbase + XSH
                + (uint32_t)((k0 + arow) * XST + wr * 64 + mi * 16 + acol) * 2);
        uint32_t bf[2][4];
#pragma unroll
        for (int np = 0; np < 2; np++)
            LDSM_X4(bf[np], sbase + WSH
                + (uint32_t)((wc * 32 + np * 16 + brow) * WST + k0 + bkoff) * 2);
#pragma unroll
        for (int mi = 0; mi < 4; mi++)
#pragma unroll
            for (int ni = 0; ni < 4; ni++)
                mma16816(acc[mi][ni], a[mi],
                         bf[ni >> 1][(ni & 1) * 2], bf[ni >> 1][(ni & 1) * 2 + 1]);
    }

    // Epilogue A: DIRECT coalesced uint2 stores in permuted feature layout.
    // Per (mi,ni) a warp writes 32 consecutive uint2 = 256B. No smem, no sync.
    {
        const int side = wc >> 1;                   // 0=q, 1=k
        const int wcq = wc & 1;                     // column-half within side
        __nv_bfloat16* dst = side ? g_k : g_q;
        uint32_t* drow = (uint32_t*)(dst + (size_t)(b * 25 + n) * 262144)
                       + pt * 4096;
#pragma unroll
        for (int mi = 0; mi < 4; mi++)
#pragma unroll
            for (int ni = 0; ni < 4; ni++) {
                uint2 val = make_uint2(packbf2(acc[mi][ni][0], acc[mi][ni][1]),
                                       packbf2(acc[mi][ni][2], acc[mi][ni][3]));
                uint32_t loc = (uint32_t)((((wr * 2 + wcq) * 4 + mi) * 4 + ni) * 64
                                          + lane * 2);
                *(uint2*)(drow + loc) = val;
            }
    }

    // ================= Phase B: v (o 128..191), 3-pass split ================
#pragma unroll
    for (int mi = 0; mi < 4; mi++)
#pragma unroll
        for (int ni = 0; ni < 2; ni++)
#pragma unroll
            for (int e = 0; e < 4; e++) acc[mi][ni][e] = 0.0f;

#pragma unroll
    for (int kk = 0; kk < 4; kk++) {
        const int k0 = kk * 16;
        uint32_t ah[4][4], al[4][4];
#pragma unroll
        for (int mi = 0; mi < 4; mi++) {
            LDSM_X4_T(ah[mi], sbase + XSH
                + (uint32_t)((k0 + arow) * XST + wr * 64 + mi * 16 + acol) * 2);
            LDSM_X4_T(al[mi], sbase + XSL
                + (uint32_t)((k0 + arow) * XST + wr * 64 + mi * 16 + acol) * 2);
        }
        uint32_t bh[4], bl[4];
        LDSM_X4(bh, sbase + WSH
            + (uint32_t)((128 + wc * 16 + brow) * WST + k0 + bkoff) * 2);
        LDSM_X4(bl, sbase + WSL
            + (uint32_t)((wc * 16 + brow) * WST + k0 + bkoff) * 2);
#pragma unroll
        for (int mi = 0; mi < 4; mi++)
#pragma unroll
            for (int ni = 0; ni < 2; ni++) {
                mma16816(acc[mi][ni], ah[mi], bh[ni * 2], bh[ni * 2 + 1]);
                mma16816(acc[mi][ni], ah[mi], bl[ni * 2], bl[ni * 2 + 1]);
                mma16816(acc[mi][ni], al[mi], bh[ni * 2], bh[ni * 2 + 1]);
            }
    }

    // Epilogue B: stage v fp16 via smem (overlays xh region), coalesced out
    __syncthreads();
    __half* cssh = (__half*)smem;                   // [64][136] half = 17408B
#pragma unroll
    for (int mi = 0; mi < 4; mi++) {
        const int px = wr * 64 + mi * 16 + g;
#pragma unroll
        for (int ni = 0; ni < 2; ni++) {
            const int orel = wc * 16 + ni * 8 + t2;
            cssh[orel * 136 + px] = __float2half(acc[mi][ni][0]);
            cssh[(orel + 1) * 136 + px] = __float2half(acc[mi][ni][1]);
            cssh[orel * 136 + px + 8] = __float2half(acc[mi][ni][2]);
            cssh[(orel + 1) * 136 + px + 8] = __float2half(acc[mi][ni][3]);
        }
    }
    __syncthreads();
#pragma unroll
    for (int i = 0; i < 4; i++) {
        int idx = tid + i * 256;                    // 0..1023
        int orel = idx >> 4, j = idx & 15;          // 64 rows x 16 uint4 (128 half)
        *(uint4*)(g_v + ((size_t)(b * 64 + orel) * 25 + n) * 4096
                  + pt * 128 + j * 8)
            = *(const uint4*)(cssh + orel * 136 + j * 8);
    }
}

// ---------------------------------------------------------------------------
// K2: Gram via HMMA on bf16 q,k. Block = (chunk of 2048 f, b); 8 iterations
// of 256-f sub-chunks. Small smem (33KB) + launch_bounds(256,4) -> one wave.
// Reads flat u32 rows -- insensitive to the permuted feature layout.
// ---------------------------------------------------------------------------
#define GST 264
#define SM_GRAM (2 * 32 * GST * 2)

__global__ __launch_bounds__(256, 4) void k_gram() {
    extern __shared__ char gsm[];
    __nv_bfloat16* qs = (__nv_bfloat16*)gsm;        // [32][264]
    __nv_bfloat16* ks = qs + 32 * GST;
    const int ch8 = blockIdx.x, bb = blockIdx.y;
    const int tid = threadIdx.x, lane = tid & 31, w = tid >> 5;

    const int moff = (w & 1) * 16, noff = ((w >> 1) & 1) * 16;
    const int li = lane & 7, sel = lane >> 3;
    const uint32_t qb = smem_u32(qs), kb = smem_u32(ks);
    const uint32_t aoff = (uint32_t)((moff + ((sel & 1) ? 8 : 0) + li) * GST
                                     + ((sel & 2) ? 8 : 0)) * 2;
    const uint32_t boff = (uint32_t)((noff + ((sel & 2) ? 8 : 0) + li) * GST
                                     + ((sel & 1) ? 8 : 0)) * 2;

    float acc[2][4] = {{0, 0, 0, 0}, {0, 0, 0, 0}};
    float nacc[7];
#pragma unroll
    for (int i = 0; i < 7; i++) nacc[i] = 0.0f;

#pragma unroll 1
    for (int t = 0; t < 8; t++) {
        const int ch = ch8 * 8 + t;                 // 256-f sub-chunk index
        __syncthreads();
        for (int i = tid; i < 800; i += 256) {      // 25 rows x 32 uint4
            int nn = i >> 5, j = i & 31;
            ((uint4*)(qs + nn * GST))[j]
                = ((const uint4*)g_q)[(size_t)(bb * 25 + nn) * 32768 + (size_t)ch * 32 + j];
            ((uint4*)(ks + nn * GST))[j]
                = ((const uint4*)g_k)[(size_t)(bb * 25 + nn) * 32768 + (size_t)ch * 32 + j];
        }
        __syncthreads();

        // norms: warp w handles rows r = w, w+8, ... (<50); full-warp uint4
        {
            int cnt = 0;
            for (int r = w; r < 50; r += 8, cnt++) {
                const __nv_bfloat16* row = (r < 25) ? qs + r * GST
                                                    : ks + (r - 25) * GST;
                uint4 u = ((const uint4*)row)[lane];
                uint32_t vv[4] = {u.x, u.y, u.z, u.w};
                float s = 0.0f;
#pragma unroll
                for (int j = 0; j < 4; j++) {
                    __nv_bfloat162 h = *(__nv_bfloat162*)&vv[j];
                    float f0 = __bfloat162float(h.x), f1 = __bfloat162float(h.y);
                    s += f0 * f0 + f1 * f1;
                }
#pragma unroll
                for (int off = 16; off; off >>= 1)
                    s += __shfl_xor_sync(0xffffffffu, s, off);
                nacc[cnt] += s;
            }
        }

        if (w < 4) {
#pragma unroll 8
            for (int k0 = 0; k0 < 256; k0 += 16) {
                uint32_t a[4], bf[4];
                LDSM_X4(a, qb + aoff + k0 * 2);
                LDSM_X4(bf, kb + boff + k0 * 2);
                mma16816(acc[0], a, bf[0], bf[1]);
                mma16816(acc[1], a, bf[2], bf[3]);
            }
        }
    }

    float* gp = g_gp + (size_t)(bb * 128 + ch8) * 1088;
    if (lane == 0) {
        int cnt = 0;
        for (int r = w; r < 50; r += 8, cnt++) {
            int isk = r >= 25;
            gp[1024 + isk * 32 + (r - isk * 25)] = nacc[cnt];
        }
    }

    if (w < 4) {
        const int row = moff + (lane >> 2), col0 = noff + (lane & 3) * 2;
#pragma unroll
        for (int ni = 0; ni < 2; ni++) {
            const int col = col0 + ni * 8;
            gp[row * 32 + col] = acc[ni][0];
            gp[row * 32 + col + 1] = acc[ni][1];
            gp[(row + 8) * 32 + col] = acc[ni][2];
            gp[(row + 8) * 32 + col + 1] = acc[ni][3];
        }
    }
}

// ---------------------------------------------------------------------------
// K3: reduce 128 chunk-partials (fixed order, 4-acc ILP) + normalize +
// softmax. 1 block per b (single kernel -> one launch).
// ---------------------------------------------------------------------------
__global__ __launch_bounds__(704) void k_redsoft() {
    __shared__ float sS[675];
    const int b = blockIdx.x, tid = threadIdx.x;

    if (tid < 675) {
        int idx;
        if (tid < 625) idx = (tid / 25) * 32 + (tid % 25);
        else if (tid < 650) idx = 1024 + (tid - 625);
        else idx = 1056 + (tid - 650);
        const float* gp = g_gp + (size_t)b * 128 * 1088 + idx;
        float s0 = 0.f, s1 = 0.f, s2 = 0.f, s3 = 0.f;
#pragma unroll 8
        for (int ch = 0; ch < 128; ch += 4) {
            s0 += gp[(size_t)(ch + 0) * 1088];
            s1 += gp[(size_t)(ch + 1) * 1088];
            s2 += gp[(size_t)(ch + 2) * 1088];
            s3 += gp[(size_t)(ch + 3) * 1088];
        }
        sS[tid] = (s0 + s1) + (s2 + s3);
    }
    __syncthreads();

    if (tid < 25) {
        const int n = tid;
        float qn = fmaxf(sqrtf(fmaxf(sS[625 + n], 0.0f)), 1e-12f);
        float v[25];
        float mx = -3.0e38f;
#pragma unroll
        for (int m = 0; m < 25; m++) {
            float kn = fmaxf(sqrtf(fmaxf(sS[650 + m], 0.0f)), 1e-12f);
            v[m] = sS[n * 25 + m] / (qn * kn);
            mx = fmaxf(mx, v[m]);
        }
        float sum = 0.0f;
#pragma unroll
        for (int m = 0; m < 25; m++) {
            v[m] = expf(v[m] - mx);
            sum += v[m];
        }
        float inv = 1.0f / sum;
#pragma unroll
        for (int m = 0; m < 25; m++)
            g_att[(b * NA + n) * NA + m] = v[m] * inv;
    }
}

// ---------------------------------------------------------------------------
// K4: out[b,d,n,p] = sum_m att[b,n,m] * v[b,d,m,p].
// 128 threads per block; each covers 6-7 n outputs (halved smem re-readers).
// f32x2 FMA, fp16 v from DRAM.
// ---------------------------------------------------------------------------
#define SM_OUT (25 * 64 * 16 + 625 * 8)

__global__ __launch_bounds__(128, 4) void k_out(float* __restrict__ out) {
    extern __shared__ float osm[];
    float4* vs4 = (float4*)osm;                             // [25][64] float4
    unsigned long long* atts2 = (unsigned long long*)(osm + 25 * 256);  // [625]
    const int pt = blockIdx.x;                              // 0..15
    const int d  = blockIdx.y;                              // 0..63
    const int b  = blockIdx.z;                              // 0..3
    const int tid = threadIdx.x;
    const int col = tid & 31;                               // u64 lane base
    const int set = tid >> 5;                               // n-subset 0..3

    // n-subsets: {7,6,6,6}
    const int nstart = (set == 0) ? 0 : (7 + (set - 1) * 6);
    const int ncnt = (set == 0) ? 7 : 6;

    // load att packed {a,a}
    for (int i = tid; i < 625; i += 128) {
        float a = g_att[b * 625 + i];
        unsigned long long a2;
        asm("mov.b64 %0, {%1, %1};" : "=l"(a2) : "f"(a));
        atts2[i] = a2;
    }
    // load v tile: 25 rows x 256 px fp16 = 800 uint4 of half8, convert to fp32
    const uint4* vph = (const uint4*)(g_v + ((size_t)(b * 64 + d) * 25) * 4096);
#pragma unroll
    for (int i = tid; i < 800; i += 128) {
        int nn = i >> 5, j = i & 31;                        // 32 uint4 per row-tile
        uint4 u = vph[nn * 512 + pt * 32 + j];
        const __half2* h2 = (const __half2*)&u;
        float2 f0 = __half22float2(h2[0]), f1 = __half22float2(h2[1]);
        float2 f2 = __half22float2(h2[2]), f3 = __half22float2(h2[3]);
        vs4[nn * 64 + j * 2]     = make_float4(f0.x, f0.y, f1.x, f1.y);
        vs4[nn * 64 + j * 2 + 1] = make_float4(f2.x, f2.y, f3.x, f3.y);
    }
    __syncthreads();

    const unsigned long long* vs8 = (const unsigned long long*)vs4;  // [25][128] u64

    unsigned long long acc[7][4];                           // [n][q]: u64 idx col+32q
#pragma unroll
    for (int j = 0; j < 7; j++)
#pragma unroll
        for (int e = 0; e < 4; e++) acc[j][e] = 0ULL;

#pragma unroll
    for (int m = 0; m < 25; m++) {
        unsigned long long v0 = vs8[m * 128 + col];
        unsigned long long v1 = vs8[m * 128 + 32 + col];
        unsigned long long v2 = vs8[m * 128 + 64 + col];
        unsigned long long v3 = vs8[m * 128 + 96 + col];
#pragma unroll
        for (int j = 0; j < 7; j++) {
            if (j < ncnt) {
                unsigned long long a2 = atts2[(nstart + j) * 25 + m];
                FMA_F32X2(acc[j][0], a2, v0, acc[j][0]);
                FMA_F32X2(acc[j][1], a2, v1, acc[j][1]);
                FMA_F32X2(acc[j][2], a2, v2, acc[j][2]);
                FMA_F32X2(acc[j][3], a2, v3, acc[j][3]);
            }
        }
    }

    float* ob = out + ((size_t)(b * 64 + d) * 25) * 4096 + pt * 256;
#pragma unroll
    for (int j = 0; j < 7; j++) {
        if (j < ncnt) {
            const int n = nstart + j;
#pragma unroll
            for (int q = 0; q < 4; q++)
                *(float2*)(ob + (size_t)n * 4096 + 2 * (col + 32 * q))
                    = *(float2*)&acc[j][q];
        }
    }
}

// ---------------------------------------------------------------------------
extern "C" void kernel_launch(void* const* d_in, const int* in_sizes, int n_in,
                              void* d_out, int out_size) {
    const float* x  = (const float*)d_in[0];
    const float* Wm = (const float*)d_in[1];
    float* out = (float*)d_out;

    cudaFuncSetAttribute(k1_mma, cudaFuncAttributeMaxDynamicSharedMemorySize, SM_K1);
    cudaFuncSetAttribute(k_gram, cudaFuncAttributeMaxDynamicSharedMemorySize, SM_GRAM);
    cudaFuncSetAttribute(k_out, cudaFuncAttributeMaxDynamicSharedMemorySize, SM_OUT);

    k1_mma<<<dim3(32, 25, 4), 256, SM_K1>>>(x, Wm);
    k_gram<<<dim3(128, 4), 256, SM_GRAM>>>();
    k_redsoft<<<4, 704>>>();
    k_out<<<dim3(16, 64, 4), 128, SM_OUT>>>(out);
}